// round 7
// baseline (speedup 1.0000x reference)
#include <cuda_runtime.h>
#include <math.h>

// Shapes (fixed per reference setup_inputs)
#define BB    4
#define NRES  300
#define NCLS  80
#define NKPT  17
#define HMW   64
#define HMHW  4096
#define NWRD  10                     // ceil(300/32)
#define NROWS (BB * NRES * NKPT)     // 20400 heatmap rows
#define NPAD  304                    // greedy loop padded to multiple of 8
#define MROWS (NPAD + 8)             // mask rows incl. prefetch overrun pad

#define IOU_THRF   0.7f
#define SCORE_THRF 0.01f
#define NEGV       (-1000000000.0f)

// Output layout (float32, flattened tuple concat):
// fl [4,300] @0 | fb [4,300,4] @1200 | fs [4,300] @6000 |
// akpts [4,300,17,3] @7200 | vkeep [4,300] @68400
#define OFF_FL 0
#define OFF_FB 1200
#define OFF_FS 6000
#define OFF_AK 7200
#define OFF_VK 68400

// Scratch (device globals — no allocation allowed)
__device__ int   g_sel[BB * NRES];
__device__ int   g_kv[BB * NRES];
__device__ float g_boxsel[BB * NRES * 4];
__device__ float g_maxv[NROWS];
__device__ int   g_midx[NROWS];
// Cold NMS working arrays (global so heatmap blocks don't pay smem for them)
__device__ float    g_sc[BB * NRES];
__device__ int      g_lb[BB * NRES];
__device__ float    g_bx[BB * NRES * 4];
__device__ int      g_order[BB * NRES];
__device__ unsigned g_mask[BB * MROWS * NWRD];

// ---------------------------------------------------------------------------
// Merged kernel: blocks 0..3 = per-batch NMS (concurrent with DRAM stream);
// blocks 4..20403 = heatmap max/argmax (ungathered). Static smem ~11 KB.
// ---------------------------------------------------------------------------
__global__ __launch_bounds__(256) void main_kernel(
    const float* __restrict__ logits,   // [4,300,80]
    const float* __restrict__ boxes,    // [4,300,4] cxcywh
    const float* __restrict__ sizes,    // [4,2]
    const float* __restrict__ hm,       // [4,300,17,4096]
    float* __restrict__ out)
{
    const int tid = threadIdx.x;

    // hot NMS arrays (smem) — heatmap blocks reuse red/sM/sIdx only
    __shared__ float sv[NRES];          // 1200
    __shared__ float ob[NRES * 4];      // 4800
    __shared__ float area[NRES];        // 1200
    __shared__ int   vv[NPAD];          // 1216
    __shared__ int   keep[NRES];        // 1200
    __shared__ int   ti[NRES];          // 1200
    __shared__ unsigned kw[NWRD];       // 40
    __shared__ float red[8];
    __shared__ float sM;
    __shared__ int   sIdx;

    if (blockIdx.x >= BB) {
        // =============== heatmap max/argmax for one (b,n,k) row ===========
        const int row = blockIdx.x - BB;
        const float4* r4 = (const float4*)hm + (size_t)row * (HMHW / 4);

        float4 A = r4[tid];
        float4 Bv = r4[tid + 256];
        float4 Cv = r4[tid + 512];
        float4 Dv = r4[tid + 768];

        // pure fmaxf tree: thread max only (values die here — low reg pressure)
        float tm = fmaxf(
            fmaxf(fmaxf(fmaxf(A.x, A.y), fmaxf(A.z, A.w)),
                  fmaxf(fmaxf(Bv.x, Bv.y), fmaxf(Bv.z, Bv.w))),
            fmaxf(fmaxf(fmaxf(Cv.x, Cv.y), fmaxf(Cv.z, Cv.w)),
                  fmaxf(fmaxf(Dv.x, Dv.y), fmaxf(Dv.z, Dv.w))));

        float wm = tm;
        #pragma unroll
        for (int o = 16; o; o >>= 1)
            wm = fmaxf(wm, __shfl_xor_sync(0xffffffffu, wm, o));
        if ((tid & 31) == 0) red[tid >> 5] = wm;
        if (tid == 0) sIdx = 0x7fffffff;
        __syncthreads();
        if (tid == 0) {
            float M = red[0];
            #pragma unroll
            for (int w = 1; w < 8; w++) M = fmaxf(M, red[w]);
            sM = M;
        }
        __syncthreads();
        const float M = sM;

        // only matching thread(s): reload own 16 floats (L1-hot) and rescan
        // descending — last write wins = smallest (first-occurrence) index
        if (tm == M) {
            int gidx = 0;
            #pragma unroll
            for (int q = 3; q >= 0; q--) {
                float4 v = r4[tid + q * 256];
                int base = 4 * (tid + q * 256);
                if (v.w == M) gidx = base + 3;
                if (v.z == M) gidx = base + 2;
                if (v.y == M) gidx = base + 1;
                if (v.x == M) gidx = base;
            }
            atomicMin(&sIdx, gidx);
        }
        __syncthreads();
        if (tid == 0) { g_maxv[row] = M; g_midx[row] = sIdx; }
        return;
    }

    // ======================= NMS for batch b ==============================
    const int b = blockIdx.x;
    const float s0 = sizes[b * 2 + 0];
    const float s1 = sizes[b * 2 + 1];
    float*    sc    = g_sc    + b * NRES;
    int*      lb    = g_lb    + b * NRES;
    float*    bx    = g_bx    + b * NRES * 4;
    int*      order_= g_order + b * NRES;
    unsigned* mcol  = g_mask  + b * MROWS * NWRD;

    // per-row: logits max/argmax (first occurrence), sigmoid, abs box
    for (int r = tid; r < NRES; r += 256) {
        const float4* lrow = (const float4*)(logits + ((size_t)b * NRES + r) * NCLS);
        float mv = -3.402823466e38f; int mi = 0;
        #pragma unroll 5
        for (int c4 = 0; c4 < NCLS / 4; c4++) {
            float4 v = lrow[c4];
            int cb = c4 * 4;
            if (v.x > mv) { mv = v.x; mi = cb;     }
            if (v.y > mv) { mv = v.y; mi = cb + 1; }
            if (v.z > mv) { mv = v.z; mi = cb + 2; }
            if (v.w > mv) { mv = v.w; mi = cb + 3; }
        }
        float score = 1.0f / (1.0f + expf(-mv));
        sc[r] = score;
        lb[r] = mi;

        const float* brow = boxes + ((size_t)b * NRES + r) * 4;
        float cx = brow[0], cy = brow[1], w = brow[2], h = brow[3];
        bx[r * 4 + 0] = (cx - w * 0.5f) * s0;
        bx[r * 4 + 1] = (cy - h * 0.5f) * s1;
        bx[r * 4 + 2] = (cx + w * 0.5f) * s0;
        bx[r * 4 + 3] = (cy + h * 0.5f) * s1;
        sv[r] = (score > SCORE_THRF) ? score : NEGV;
    }
    __syncthreads();

    // maxc = max(|abs_boxes|) + 1
    {
        float lmax = 0.0f;
        for (int i = tid; i < NRES * 4; i += 256)
            lmax = fmaxf(lmax, fabsf(bx[i]));
        #pragma unroll
        for (int o = 16; o; o >>= 1)
            lmax = fmaxf(lmax, __shfl_down_sync(0xffffffffu, lmax, o));
        if ((tid & 31) == 0) red[tid >> 5] = lmax;
        __syncthreads();
        if (tid == 0) {
            float v = red[0];
            #pragma unroll
            for (int w = 1; w < 8; w++) v = fmaxf(v, red[w]);
            sM = v + 1.0f;
        }
        __syncthreads();
    }
    const float maxc = sM;

    // stable descending rank (replicates stable argsort(-s))
    for (int r = tid; r < NRES; r += 256) {
        float si = sv[r];
        int rk = 0;
        for (int j = 0; j < NRES; j++) {
            float sj = sv[j];
            rk += (sj > si) || (sj == si && j < r);
        }
        order_[rk] = r;
    }
    __syncthreads();

    // sorted, class-offset boxes + areas (areas from offset coords)
    for (int t = tid; t < NRES; t += 256) {
        int i = order_[t];
        vv[t] = sv[i] != NEGV;
        float off = (float)lb[i] * maxc;
        float x1 = bx[i * 4 + 0] + off;
        float y1 = bx[i * 4 + 1] + off;
        float x2 = bx[i * 4 + 2] + off;
        float y2 = bx[i * 4 + 3] + off;
        ob[t * 4 + 0] = x1;
        ob[t * 4 + 1] = y1;
        ob[t * 4 + 2] = x2;
        ob[t * 4 + 3] = y2;
        area[t] = (x2 - x1) * (y2 - y1);
    }
    if (tid < NPAD - NRES) vv[NRES + tid] = 0;
    __syncthreads();

    // suppression bitmask rows -> global; pad rows [NRES, MROWS) zeroed
    for (int task = tid; task < NRES * NWRD; task += 256) {
        int r = task % NRES;
        int w = task / NRES;
        float x1 = ob[r * 4 + 0], y1 = ob[r * 4 + 1];
        float x2 = ob[r * 4 + 2], y2 = ob[r * 4 + 3];
        float ar = area[r];
        unsigned m = 0;
        int j0 = w * 32;
        #pragma unroll 8
        for (int jj = 0; jj < 32; jj++) {
            int j = j0 + jj;
            if (j > r && j < NRES) {
                float iw = fmaxf(fminf(x2, ob[j * 4 + 2]) - fmaxf(x1, ob[j * 4 + 0]), 0.0f);
                float ih = fmaxf(fminf(y2, ob[j * 4 + 3]) - fmaxf(y1, ob[j * 4 + 1]), 0.0f);
                float inter = iw * ih;
                float iou = inter / (ar + area[j] - inter + 1e-9f);
                if (iou > IOU_THRF) m |= (1u << jj);
            }
        }
        mcol[r * NWRD + w] = m;
    }
    for (int p = tid; p < (MROWS - NRES) * NWRD; p += 256)
        mcol[NRES * NWRD + p] = 0;
    __syncthreads();

    // greedy pass: warp 0, lanes 0..9 own suppression words; 8-deep prefetch
    if (tid < 32) {
        const bool ld = tid < NWRD;
        unsigned buf[8];
        #pragma unroll
        for (int d = 0; d < 8; d++)
            buf[d] = ld ? mcol[d * NWRD + tid] : 0u;
        unsigned sw = 0;
        for (int i0 = 0; i0 < NPAD; i0 += 8) {
            #pragma unroll
            for (int u = 0; u < 8; u++) {
                int i = i0 + u;
                unsigned m = buf[u];
                buf[u] = ld ? mcol[(i + 8) * NWRD + tid] : 0u;   // prefetch
                unsigned word = __shfl_sync(0xffffffffu, sw, i >> 5);
                int suppressed = (word >> (i & 31)) & 1;
                int is_keep = vv[i] & (suppressed ^ 1);
                if (tid == 0 && i < NRES) keep[i] = is_keep;
                if (is_keep) sw |= m;   // m==0 for lanes >= NWRD / pad rows
            }
        }
    }
    __syncthreads();

    // pack keep bitmask words
    if (tid < NWRD) {
        unsigned m = 0;
        for (int jj = 0; jj < 32; jj++) {
            int i = tid * 32 + jj;
            if (i < NRES && keep[i]) m |= (1u << jj);
        }
        kw[tid] = m;
    }
    __syncthreads();

    // ti: kept (sorted order) then suppressed (ascending) — parallel prefix
    for (int t = tid; t < NRES; t += 256) {
        int wt = t >> 5, bt_ = t & 31;
        int cnt = 0, K = 0;
        #pragma unroll
        for (int w = 0; w < NWRD; w++) {
            int pc = __popc(kw[w]);
            K += pc;
            if (w < wt) cnt += pc;
        }
        cnt += __popc(kw[wt] & ((1u << bt_) - 1u));
        int p = keep[t] ? cnt : (K + t - cnt);
        ti[p] = t;
    }
    __syncthreads();

    // outputs + scratch for finalize
    for (int t = tid; t < NRES; t += 256) {
        int tt  = ti[t];
        int kv  = keep[tt];
        int sel = order_[tt];
        int gi  = b * NRES + t;

        g_sel[gi] = sel;
        g_kv[gi]  = kv;

        float b0 = bx[sel * 4 + 0], b1 = bx[sel * 4 + 1];
        float b2 = bx[sel * 4 + 2], b3 = bx[sel * 4 + 3];
        g_boxsel[gi * 4 + 0] = b0;
        g_boxsel[gi * 4 + 1] = b1;
        g_boxsel[gi * 4 + 2] = b2;
        g_boxsel[gi * 4 + 3] = b3;

        out[OFF_FL + gi] = kv ? (float)lb[sel] : -1.0f;
        float* fb = out + OFF_FB + (size_t)gi * 4;
        fb[0] = kv ? b0 : 0.0f;
        fb[1] = kv ? b1 : 0.0f;
        fb[2] = kv ? b2 : 0.0f;
        fb[3] = kv ? b3 : 0.0f;
        out[OFF_FS + gi] = kv ? sc[sel] : 0.0f;
        out[OFF_VK + gi] = kv ? 1.0f : 0.0f;
    }
}

// ---------------------------------------------------------------------------
// Finalize: gather (maxv, idx) by sel, compute akpts. One thread per output.
// ---------------------------------------------------------------------------
__global__ __launch_bounds__(256) void finalize_kernel(
    const float* __restrict__ koff,   // [4,300,17,2]
    float* __restrict__ out)
{
    int i = blockIdx.x * 256 + threadIdx.x;   // (b, t, k) flattened
    if (i >= NROWS) return;
    int k  = i % NKPT;
    int gi = i / NKPT;
    int b  = gi / NRES;

    int sel = g_sel[gi];
    int kv  = g_kv[gi];
    int row = (b * NRES + sel) * NKPT + k;

    float mv = g_maxv[row];
    int   bi = g_midx[row];
    const float* ko = koff + (size_t)row * 2;

    float nx = fminf(fmaxf(__int2float_rn(bi % HMW) / (float)(HMW - 1) + ko[0], 0.0f), 1.0f);
    float ny = fminf(fmaxf(__int2float_rn(bi / HMW) / (float)(HMW - 1) + ko[1], 0.0f), 1.0f);

    float x1 = g_boxsel[gi * 4 + 0], y1 = g_boxsel[gi * 4 + 1];
    float x2 = g_boxsel[gi * 4 + 2], y2 = g_boxsel[gi * 4 + 3];
    float ax = x1 + nx * (x2 - x1);
    float ay = y1 + ny * (y2 - y1);

    float* o = out + OFF_AK + (size_t)i * 3;
    o[0] = kv ? ax : 0.0f;
    o[1] = kv ? ay : 0.0f;
    o[2] = kv ? mv : 0.0f;
}

// ---------------------------------------------------------------------------
extern "C" void kernel_launch(void* const* d_in, const int* in_sizes, int n_in,
                              void* d_out, int out_size)
{
    const float* logits = (const float*)d_in[0];  // pred_logits
    const float* boxes  = (const float*)d_in[1];  // pred_boxes
    const float* hm     = (const float*)d_in[2];  // pred_keypoint_heatmaps
    const float* koff   = (const float*)d_in[3];  // pred_keypoint_offsets
    const float* sizes  = (const float*)d_in[4];  // orig_target_sizes
    float* out = (float*)d_out;

    main_kernel<<<BB + NROWS, 256>>>(logits, boxes, sizes, hm, out);
    finalize_kernel<<<(NROWS + 255) / 256, 256>>>(koff, out);
}

// round 8
// speedup vs baseline: 1.0124x; 1.0124x over previous
#include <cuda_runtime.h>
#include <math.h>

// Shapes (fixed per reference setup_inputs)
#define BB    4
#define NRES  300
#define NCLS  80
#define NKPT  17
#define HMW   64
#define HMHW  4096
#define NWRD  10                     // ceil(300/32)
#define NROWS (BB * NRES * NKPT)     // 20400 heatmap rows
#define NPAD  304                    // greedy loop padded to multiple of 8
#define MROWS (NPAD + 8)             // mask rows incl. prefetch overrun pad

#define IOU_THRF   0.7f
#define SCORE_THRF 0.01f
#define NEGV       (-1000000000.0f)

// Output layout (float32, flattened tuple concat):
// fl [4,300] @0 | fb [4,300,4] @1200 | fs [4,300] @6000 |
// akpts [4,300,17,3] @7200 | vkeep [4,300] @68400
#define OFF_FL 0
#define OFF_FB 1200
#define OFF_FS 6000
#define OFF_AK 7200
#define OFF_VK 68400

// Scratch (device globals — no allocation allowed)
__device__ int   g_sel[BB * NRES];
__device__ int   g_kv[BB * NRES];
__device__ float g_boxsel[BB * NRES * 4];
__device__ float g_maxv[NROWS];
__device__ int   g_midx[NROWS];
// Cold NMS working arrays (global so heatmap blocks don't pay smem for them)
__device__ float    g_sc[BB * NRES];
__device__ int      g_lb[BB * NRES];
__device__ float    g_bx[BB * NRES * 4];
__device__ int      g_order[BB * NRES];
__device__ unsigned g_mask[BB * MROWS * NWRD];

// ---------------------------------------------------------------------------
// Merged kernel: blocks 0..3 = per-batch NMS (concurrent with DRAM stream);
// blocks 4..20403 = heatmap max/argmax (ungathered). Static smem ~11 KB.
// ---------------------------------------------------------------------------
__global__ __launch_bounds__(256) void main_kernel(
    const float* __restrict__ logits,   // [4,300,80]
    const float* __restrict__ boxes,    // [4,300,4] cxcywh
    const float* __restrict__ sizes,    // [4,2]
    const float* __restrict__ hm,       // [4,300,17,4096]
    float* __restrict__ out)
{
    const int tid = threadIdx.x;

    // hot NMS arrays (smem) — heatmap blocks reuse red/sM/sIdx only
    __shared__ float sv[NRES];          // 1200
    __shared__ float ob[NRES * 4];      // 4800
    __shared__ float area[NRES];        // 1200
    __shared__ int   vv[NPAD];          // 1216
    __shared__ int   keep[NRES];        // 1200
    __shared__ int   ti[NRES];          // 1200
    __shared__ unsigned kw[NWRD];       // 40
    __shared__ float red[8];
    __shared__ float sM;
    __shared__ int   sIdx;

    if (blockIdx.x >= BB) {
        // =============== heatmap max/argmax for one (b,n,k) row ===========
        const int row = blockIdx.x - BB;
        const float4* r4 = (const float4*)hm + (size_t)row * (HMHW / 4);

        float4 A = r4[tid];
        float4 Bv = r4[tid + 256];
        float4 Cv = r4[tid + 512];
        float4 Dv = r4[tid + 768];

        // pure fmaxf tree: thread max only (values die here — low reg pressure)
        float tm = fmaxf(
            fmaxf(fmaxf(fmaxf(A.x, A.y), fmaxf(A.z, A.w)),
                  fmaxf(fmaxf(Bv.x, Bv.y), fmaxf(Bv.z, Bv.w))),
            fmaxf(fmaxf(fmaxf(Cv.x, Cv.y), fmaxf(Cv.z, Cv.w)),
                  fmaxf(fmaxf(Dv.x, Dv.y), fmaxf(Dv.z, Dv.w))));

        float wm = tm;
        #pragma unroll
        for (int o = 16; o; o >>= 1)
            wm = fmaxf(wm, __shfl_xor_sync(0xffffffffu, wm, o));
        if ((tid & 31) == 0) red[tid >> 5] = wm;
        if (tid == 0) sIdx = 0x7fffffff;
        __syncthreads();
        if (tid == 0) {
            float M = red[0];
            #pragma unroll
            for (int w = 1; w < 8; w++) M = fmaxf(M, red[w]);
            sM = M;
        }
        __syncthreads();
        const float M = sM;

        // only matching thread(s): reload own 16 floats (L1-hot) and rescan
        // descending — last write wins = smallest (first-occurrence) index
        if (tm == M) {
            int gidx = 0;
            #pragma unroll
            for (int q = 3; q >= 0; q--) {
                float4 v = r4[tid + q * 256];
                int base = 4 * (tid + q * 256);
                if (v.w == M) gidx = base + 3;
                if (v.z == M) gidx = base + 2;
                if (v.y == M) gidx = base + 1;
                if (v.x == M) gidx = base;
            }
            atomicMin(&sIdx, gidx);
        }
        __syncthreads();
        if (tid == 0) { g_maxv[row] = M; g_midx[row] = sIdx; }
        return;
    }

    // ======================= NMS for batch b ==============================
    const int b = blockIdx.x;
    const float s0 = sizes[b * 2 + 0];
    const float s1 = sizes[b * 2 + 1];
    float*    sc    = g_sc    + b * NRES;
    int*      lb    = g_lb    + b * NRES;
    float*    bx    = g_bx    + b * NRES * 4;
    int*      order_= g_order + b * NRES;
    unsigned* mcol  = g_mask  + b * MROWS * NWRD;

    // per-row: logits max/argmax (first occurrence), sigmoid, abs box
    for (int r = tid; r < NRES; r += 256) {
        const float4* lrow = (const float4*)(logits + ((size_t)b * NRES + r) * NCLS);
        float mv = -3.402823466e38f; int mi = 0;
        #pragma unroll 5
        for (int c4 = 0; c4 < NCLS / 4; c4++) {
            float4 v = lrow[c4];
            int cb = c4 * 4;
            if (v.x > mv) { mv = v.x; mi = cb;     }
            if (v.y > mv) { mv = v.y; mi = cb + 1; }
            if (v.z > mv) { mv = v.z; mi = cb + 2; }
            if (v.w > mv) { mv = v.w; mi = cb + 3; }
        }
        float score = 1.0f / (1.0f + expf(-mv));
        sc[r] = score;
        lb[r] = mi;

        const float* brow = boxes + ((size_t)b * NRES + r) * 4;
        float cx = brow[0], cy = brow[1], w = brow[2], h = brow[3];
        bx[r * 4 + 0] = (cx - w * 0.5f) * s0;
        bx[r * 4 + 1] = (cy - h * 0.5f) * s1;
        bx[r * 4 + 2] = (cx + w * 0.5f) * s0;
        bx[r * 4 + 3] = (cy + h * 0.5f) * s1;
        sv[r] = (score > SCORE_THRF) ? score : NEGV;
    }
    __syncthreads();

    // maxc = max(|abs_boxes|) + 1
    {
        float lmax = 0.0f;
        for (int i = tid; i < NRES * 4; i += 256)
            lmax = fmaxf(lmax, fabsf(bx[i]));
        #pragma unroll
        for (int o = 16; o; o >>= 1)
            lmax = fmaxf(lmax, __shfl_down_sync(0xffffffffu, lmax, o));
        if ((tid & 31) == 0) red[tid >> 5] = lmax;
        __syncthreads();
        if (tid == 0) {
            float v = red[0];
            #pragma unroll
            for (int w = 1; w < 8; w++) v = fmaxf(v, red[w]);
            sM = v + 1.0f;
        }
        __syncthreads();
    }
    const float maxc = sM;

    // stable descending rank (replicates stable argsort(-s))
    for (int r = tid; r < NRES; r += 256) {
        float si = sv[r];
        int rk = 0;
        for (int j = 0; j < NRES; j++) {
            float sj = sv[j];
            rk += (sj > si) || (sj == si && j < r);
        }
        order_[rk] = r;
    }
    __syncthreads();

    // sorted, class-offset boxes + areas (areas from offset coords)
    for (int t = tid; t < NRES; t += 256) {
        int i = order_[t];
        vv[t] = sv[i] != NEGV;
        float off = (float)lb[i] * maxc;
        float x1 = bx[i * 4 + 0] + off;
        float y1 = bx[i * 4 + 1] + off;
        float x2 = bx[i * 4 + 2] + off;
        float y2 = bx[i * 4 + 3] + off;
        ob[t * 4 + 0] = x1;
        ob[t * 4 + 1] = y1;
        ob[t * 4 + 2] = x2;
        ob[t * 4 + 3] = y2;
        area[t] = (x2 - x1) * (y2 - y1);
    }
    if (tid < NPAD - NRES) vv[NRES + tid] = 0;
    __syncthreads();

    // suppression bitmask rows -> global; pad rows [NRES, MROWS) zeroed
    for (int task = tid; task < NRES * NWRD; task += 256) {
        int r = task % NRES;
        int w = task / NRES;
        float x1 = ob[r * 4 + 0], y1 = ob[r * 4 + 1];
        float x2 = ob[r * 4 + 2], y2 = ob[r * 4 + 3];
        float ar = area[r];
        unsigned m = 0;
        int j0 = w * 32;
        #pragma unroll 8
        for (int jj = 0; jj < 32; jj++) {
            int j = j0 + jj;
            if (j > r && j < NRES) {
                float iw = fmaxf(fminf(x2, ob[j * 4 + 2]) - fmaxf(x1, ob[j * 4 + 0]), 0.0f);
                float ih = fmaxf(fminf(y2, ob[j * 4 + 3]) - fmaxf(y1, ob[j * 4 + 1]), 0.0f);
                float inter = iw * ih;
                float iou = inter / (ar + area[j] - inter + 1e-9f);
                if (iou > IOU_THRF) m |= (1u << jj);
            }
        }
        mcol[r * NWRD + w] = m;
    }
    for (int p = tid; p < (MROWS - NRES) * NWRD; p += 256)
        mcol[NRES * NWRD + p] = 0;
    __syncthreads();

    // greedy pass: warp 0, lanes 0..9 own suppression words; 8-deep prefetch
    if (tid < 32) {
        const bool ld = tid < NWRD;
        unsigned buf[8];
        #pragma unroll
        for (int d = 0; d < 8; d++)
            buf[d] = ld ? mcol[d * NWRD + tid] : 0u;
        unsigned sw = 0;
        for (int i0 = 0; i0 < NPAD; i0 += 8) {
            #pragma unroll
            for (int u = 0; u < 8; u++) {
                int i = i0 + u;
                unsigned m = buf[u];
                buf[u] = ld ? mcol[(i + 8) * NWRD + tid] : 0u;   // prefetch
                unsigned word = __shfl_sync(0xffffffffu, sw, i >> 5);
                int suppressed = (word >> (i & 31)) & 1;
                int is_keep = vv[i] & (suppressed ^ 1);
                if (tid == 0 && i < NRES) keep[i] = is_keep;
                if (is_keep) sw |= m;   // m==0 for lanes >= NWRD / pad rows
            }
        }
    }
    __syncthreads();

    // pack keep bitmask words
    if (tid < NWRD) {
        unsigned m = 0;
        for (int jj = 0; jj < 32; jj++) {
            int i = tid * 32 + jj;
            if (i < NRES && keep[i]) m |= (1u << jj);
        }
        kw[tid] = m;
    }
    __syncthreads();

    // ti: kept (sorted order) then suppressed (ascending) — parallel prefix
    for (int t = tid; t < NRES; t += 256) {
        int wt = t >> 5, bt_ = t & 31;
        int cnt = 0, K = 0;
        #pragma unroll
        for (int w = 0; w < NWRD; w++) {
            int pc = __popc(kw[w]);
            K += pc;
            if (w < wt) cnt += pc;
        }
        cnt += __popc(kw[wt] & ((1u << bt_) - 1u));
        int p = keep[t] ? cnt : (K + t - cnt);
        ti[p] = t;
    }
    __syncthreads();

    // outputs + scratch for finalize
    for (int t = tid; t < NRES; t += 256) {
        int tt  = ti[t];
        int kv  = keep[tt];
        int sel = order_[tt];
        int gi  = b * NRES + t;

        g_sel[gi] = sel;
        g_kv[gi]  = kv;

        float b0 = bx[sel * 4 + 0], b1 = bx[sel * 4 + 1];
        float b2 = bx[sel * 4 + 2], b3 = bx[sel * 4 + 3];
        g_boxsel[gi * 4 + 0] = b0;
        g_boxsel[gi * 4 + 1] = b1;
        g_boxsel[gi * 4 + 2] = b2;
        g_boxsel[gi * 4 + 3] = b3;

        out[OFF_FL + gi] = kv ? (float)lb[sel] : -1.0f;
        float* fb = out + OFF_FB + (size_t)gi * 4;
        fb[0] = kv ? b0 : 0.0f;
        fb[1] = kv ? b1 : 0.0f;
        fb[2] = kv ? b2 : 0.0f;
        fb[3] = kv ? b3 : 0.0f;
        out[OFF_FS + gi] = kv ? sc[sel] : 0.0f;
        out[OFF_VK + gi] = kv ? 1.0f : 0.0f;
    }
}

// ---------------------------------------------------------------------------
// Finalize: gather (maxv, idx) by sel, compute akpts. One thread per output.
// ---------------------------------------------------------------------------
__global__ __launch_bounds__(256) void finalize_kernel(
    const float* __restrict__ koff,   // [4,300,17,2]
    float* __restrict__ out)
{
    int i = blockIdx.x * 256 + threadIdx.x;   // (b, t, k) flattened
    if (i >= NROWS) return;
    int k  = i % NKPT;
    int gi = i / NKPT;
    int b  = gi / NRES;

    int sel = g_sel[gi];
    int kv  = g_kv[gi];
    int row = (b * NRES + sel) * NKPT + k;

    float mv = g_maxv[row];
    int   bi = g_midx[row];
    const float* ko = koff + (size_t)row * 2;

    float nx = fminf(fmaxf(__int2float_rn(bi % HMW) / (float)(HMW - 1) + ko[0], 0.0f), 1.0f);
    float ny = fminf(fmaxf(__int2float_rn(bi / HMW) / (float)(HMW - 1) + ko[1], 0.0f), 1.0f);

    float x1 = g_boxsel[gi * 4 + 0], y1 = g_boxsel[gi * 4 + 1];
    float x2 = g_boxsel[gi * 4 + 2], y2 = g_boxsel[gi * 4 + 3];
    float ax = x1 + nx * (x2 - x1);
    float ay = y1 + ny * (y2 - y1);

    float* o = out + OFF_AK + (size_t)i * 3;
    o[0] = kv ? ax : 0.0f;
    o[1] = kv ? ay : 0.0f;
    o[2] = kv ? mv : 0.0f;
}

// ---------------------------------------------------------------------------
extern "C" void kernel_launch(void* const* d_in, const int* in_sizes, int n_in,
                              void* d_out, int out_size)
{
    const float* logits = (const float*)d_in[0];  // pred_logits
    const float* boxes  = (const float*)d_in[1];  // pred_boxes
    const float* hm     = (const float*)d_in[2];  // pred_keypoint_heatmaps
    const float* koff   = (const float*)d_in[3];  // pred_keypoint_offsets
    const float* sizes  = (const float*)d_in[4];  // orig_target_sizes
    float* out = (float*)d_out;

    main_kernel<<<BB + NROWS, 256>>>(logits, boxes, sizes, hm, out);
    finalize_kernel<<<(NROWS + 255) / 256, 256>>>(koff, out);
}

// round 9
// speedup vs baseline: 1.1256x; 1.1118x over previous
#include <cuda_runtime.h>
#include <math.h>

// Shapes (fixed per reference setup_inputs)
#define BB    4
#define NRES  300
#define NCLS  80
#define NKPT  17
#define HMW   64
#define HMHW  4096
#define NWRD  10                     // ceil(300/32)
#define NROWS (BB * NRES * NKPT)     // 20400 heatmap rows

#define IOU_THRF   0.7f
#define SCORE_THRF 0.01f
#define NEGV       (-1000000000.0f)

// Output layout (float32, flattened tuple concat):
// fl [4,300] @0 | fb [4,300,4] @1200 | fs [4,300] @6000 |
// akpts [4,300,17,3] @7200 | vkeep [4,300] @68400
#define OFF_FL 0
#define OFF_FB 1200
#define OFF_FS 6000
#define OFF_AK 7200
#define OFF_VK 68400

// Scratch (device globals — no allocation allowed)
__device__ int   g_sel[BB * NRES];
__device__ int   g_kv[BB * NRES];
__device__ float g_boxsel[BB * NRES * 4];
__device__ float g_maxv[NROWS];
__device__ int   g_midx[NROWS];
// Cold NMS working arrays (global so heatmap blocks don't pay smem for them)
__device__ float g_sc[BB * NRES];
__device__ int   g_lb[BB * NRES];
__device__ float g_bx[BB * NRES * 4];
__device__ int   g_order[BB * NRES];

// ---------------------------------------------------------------------------
// Merged kernel: blocks 0..3 = per-batch NMS (concurrent with DRAM stream);
// blocks 4..20403 = heatmap max/argmax (ungathered). Static smem ~23 KB ->
// still 8 blocks/SM on the 228 KB unified carveout (thread-limited).
// ---------------------------------------------------------------------------
__global__ __launch_bounds__(256) void main_kernel(
    const float* __restrict__ logits,   // [4,300,80]
    const float* __restrict__ boxes,    // [4,300,4] cxcywh
    const float* __restrict__ sizes,    // [4,2]
    const float* __restrict__ hm,       // [4,300,17,4096]
    float* __restrict__ out)
{
    const int tid = threadIdx.x;

    // --- NMS shared state (SoA; conflict-free access patterns) ---
    __shared__ float obx1[NRES], oby1[NRES], obx2[NRES], oby2[NRES];
    __shared__ float sarea[NRES];
    __shared__ float sv[NRES];
    __shared__ int   vv[NRES + 1];               // +1: pad for off-chain prefetch
    __shared__ unsigned mask[(NRES + 1) * NWRD]; // +1 zero row for prefetch
    __shared__ int   keep[NRES];
    __shared__ int   ti[NRES];
    __shared__ unsigned kw[NWRD];
    __shared__ float red[8];
    __shared__ float sM;
    __shared__ int   sIdx;

    if (blockIdx.x >= BB) {
        // =============== heatmap max/argmax for one (b,n,k) row ===========
        const int row = blockIdx.x - BB;
        const float4* r4 = (const float4*)hm + (size_t)row * (HMHW / 4);

        float4 A  = r4[tid];
        float4 Bv = r4[tid + 256];
        float4 Cv = r4[tid + 512];
        float4 Dv = r4[tid + 768];

        float tm = fmaxf(
            fmaxf(fmaxf(fmaxf(A.x, A.y), fmaxf(A.z, A.w)),
                  fmaxf(fmaxf(Bv.x, Bv.y), fmaxf(Bv.z, Bv.w))),
            fmaxf(fmaxf(fmaxf(Cv.x, Cv.y), fmaxf(Cv.z, Cv.w)),
                  fmaxf(fmaxf(Dv.x, Dv.y), fmaxf(Dv.z, Dv.w))));

        float wm = tm;
        #pragma unroll
        for (int o = 16; o; o >>= 1)
            wm = fmaxf(wm, __shfl_xor_sync(0xffffffffu, wm, o));
        if ((tid & 31) == 0) red[tid >> 5] = wm;
        if (tid == 0) sIdx = 0x7fffffff;
        __syncthreads();
        if (tid == 0) {
            float M = red[0];
            #pragma unroll
            for (int w = 1; w < 8; w++) M = fmaxf(M, red[w]);
            sM = M;
        }
        __syncthreads();
        const float M = sM;

        // only matching thread(s): reload own 16 floats (L1-hot), rescan
        // descending — last write wins = first-occurrence index
        if (tm == M) {
            int gidx = 0;
            #pragma unroll
            for (int q = 3; q >= 0; q--) {
                float4 v = r4[tid + q * 256];
                int base = 4 * (tid + q * 256);
                if (v.w == M) gidx = base + 3;
                if (v.z == M) gidx = base + 2;
                if (v.y == M) gidx = base + 1;
                if (v.x == M) gidx = base;
            }
            atomicMin(&sIdx, gidx);
        }
        __syncthreads();
        if (tid == 0) { g_maxv[row] = M; g_midx[row] = sIdx; }
        return;
    }

    // ======================= NMS for batch b ==============================
    const int b = blockIdx.x;
    const float s0 = sizes[b * 2 + 0];
    const float s1 = sizes[b * 2 + 1];
    float* sc     = g_sc    + b * NRES;
    int*   lb     = g_lb    + b * NRES;
    float* bx     = g_bx    + b * NRES * 4;
    int*   order_ = g_order + b * NRES;

    // ---- phase 1: logits argmax + sigmoid + abs box; fused |box| max ----
    float lmax = 0.0f;
    for (int r = tid; r < NRES; r += 256) {
        const float4* lrow = (const float4*)(logits + ((size_t)b * NRES + r) * NCLS);
        float mv = -3.402823466e38f; int mi = 0;
        #pragma unroll 5
        for (int c4 = 0; c4 < NCLS / 4; c4++) {
            float4 v = lrow[c4];
            int cb = c4 * 4;
            if (v.x > mv) { mv = v.x; mi = cb;     }
            if (v.y > mv) { mv = v.y; mi = cb + 1; }
            if (v.z > mv) { mv = v.z; mi = cb + 2; }
            if (v.w > mv) { mv = v.w; mi = cb + 3; }
        }
        float score = 1.0f / (1.0f + expf(-mv));
        sc[r] = score;
        lb[r] = mi;

        const float* brow = boxes + ((size_t)b * NRES + r) * 4;
        float cx = brow[0], cy = brow[1], w = brow[2], h = brow[3];
        float x1 = (cx - w * 0.5f) * s0;
        float y1 = (cy - h * 0.5f) * s1;
        float x2 = (cx + w * 0.5f) * s0;
        float y2 = (cy + h * 0.5f) * s1;
        bx[r * 4 + 0] = x1;
        bx[r * 4 + 1] = y1;
        bx[r * 4 + 2] = x2;
        bx[r * 4 + 3] = y2;
        lmax = fmaxf(lmax, fmaxf(fmaxf(fabsf(x1), fabsf(y1)),
                                 fmaxf(fabsf(x2), fabsf(y2))));
        sv[r] = (score > SCORE_THRF) ? score : NEGV;
    }
    // block max -> maxc
    #pragma unroll
    for (int o = 16; o; o >>= 1)
        lmax = fmaxf(lmax, __shfl_xor_sync(0xffffffffu, lmax, o));
    if ((tid & 31) == 0) red[tid >> 5] = lmax;
    __syncthreads();
    if (tid == 0) {
        float v = red[0];
        #pragma unroll
        for (int w = 1; w < 8; w++) v = fmaxf(v, red[w]);
        sM = v + 1.0f;
    }
    __syncthreads();
    const float maxc = sM;

    // ---- phase 2: stable descending rank (stable argsort(-s)) ----
    for (int r = tid; r < NRES; r += 256) {
        float si = sv[r];
        int rk = 0;
        #pragma unroll 4
        for (int j = 0; j < NRES; j++) {
            float sj = sv[j];
            rk += (sj > si) || (sj == si && j < r);
        }
        order_[rk] = r;
    }
    __syncthreads();

    // ---- phase 3: sorted class-offset boxes (SoA) + areas + valid ----
    for (int t = tid; t < NRES; t += 256) {
        int i = order_[t];
        vv[t] = sv[i] != NEGV;
        float off = (float)lb[i] * maxc;
        float x1 = bx[i * 4 + 0] + off;
        float y1 = bx[i * 4 + 1] + off;
        float x2 = bx[i * 4 + 2] + off;
        float y2 = bx[i * 4 + 3] + off;
        obx1[t] = x1; oby1[t] = y1; obx2[t] = x2; oby2[t] = y2;
        sarea[t] = (x2 - x1) * (y2 - y1);
    }
    if (tid == 0) vv[NRES] = 0;
    __syncthreads();

    // ---- phase 4: suppression bitmask (SoA: lane loads conflict-free) ----
    // task -> (r = task % NRES, w = task / NRES): lanes have consecutive r
    // (conflict-free per-r loads), uniform w (broadcast per-j loads).
    for (int task = tid; task < NRES * NWRD; task += 256) {
        int r = task % NRES;
        int w = task / NRES;
        float x1 = obx1[r], y1 = oby1[r], x2 = obx2[r], y2 = oby2[r];
        float ar = sarea[r];
        unsigned m = 0;
        int j0 = w * 32;
        #pragma unroll 8
        for (int jj = 0; jj < 32; jj++) {
            int j = j0 + jj;
            if (j > r && j < NRES) {
                float iw = fmaxf(fminf(x2, obx2[j]) - fmaxf(x1, obx1[j]), 0.0f);
                float ih = fmaxf(fminf(y2, oby2[j]) - fmaxf(y1, oby1[j]), 0.0f);
                float inter = iw * ih;
                float iou = inter / (ar + sarea[j] - inter + 1e-9f);
                if (iou > IOU_THRF) m |= (1u << jj);
            }
        }
        mask[r * NWRD + w] = m;
    }
    if (tid < NWRD) mask[NRES * NWRD + tid] = 0;   // zero pad row
    __syncthreads();

    // ---- phase 5: greedy pass (warp 0; lanes 0..9 own suppression words) ----
    // chain per iter: shfl(26) + shift/and + select/or ~= 42 cyc; mask word
    // and vv for i+1 prefetched off-chain.
    if (tid < 32) {
        const bool ld = tid < NWRD;
        unsigned sw = 0;
        unsigned mnext = ld ? mask[tid] : 0u;
        int      vnext = vv[0];
        for (int i = 0; i < NRES; i++) {
            unsigned m = mnext;
            int      v = vnext;
            mnext = ld ? mask[(i + 1) * NWRD + tid] : 0u;  // off-chain
            vnext = vv[i + 1];                             // off-chain
            unsigned word = __shfl_sync(0xffffffffu, sw, i >> 5);
            int is_keep = v & ~((int)(word >> (i & 31)) & 1);
            if (tid == 0) keep[i] = is_keep;
            sw |= is_keep ? m : 0u;
        }
    }
    __syncthreads();

    // ---- phase 6: pack keep words ----
    if (tid < NWRD) {
        unsigned m = 0;
        for (int jj = 0; jj < 32; jj++) {
            int i = tid * 32 + jj;
            if (i < NRES && keep[i]) m |= (1u << jj);
        }
        kw[tid] = m;
    }
    __syncthreads();

    // ---- phase 7: ti = kept (sorted order) then suppressed (ascending) ----
    for (int t = tid; t < NRES; t += 256) {
        int wt = t >> 5, bt_ = t & 31;
        int cnt = 0, K = 0;
        #pragma unroll
        for (int w = 0; w < NWRD; w++) {
            int pc = __popc(kw[w]);
            K += pc;
            if (w < wt) cnt += pc;
        }
        cnt += __popc(kw[wt] & ((1u << bt_) - 1u));
        int p = keep[t] ? cnt : (K + t - cnt);
        ti[p] = t;
    }
    __syncthreads();

    // ---- phase 8: outputs + scratch for finalize ----
    for (int t = tid; t < NRES; t += 256) {
        int tt  = ti[t];
        int kv  = keep[tt];
        int sel = order_[tt];
        int gi  = b * NRES + t;

        g_sel[gi] = sel;
        g_kv[gi]  = kv;

        float b0 = bx[sel * 4 + 0], b1 = bx[sel * 4 + 1];
        float b2 = bx[sel * 4 + 2], b3 = bx[sel * 4 + 3];
        g_boxsel[gi * 4 + 0] = b0;
        g_boxsel[gi * 4 + 1] = b1;
        g_boxsel[gi * 4 + 2] = b2;
        g_boxsel[gi * 4 + 3] = b3;

        out[OFF_FL + gi] = kv ? (float)lb[sel] : -1.0f;
        float* fb = out + OFF_FB + (size_t)gi * 4;
        fb[0] = kv ? b0 : 0.0f;
        fb[1] = kv ? b1 : 0.0f;
        fb[2] = kv ? b2 : 0.0f;
        fb[3] = kv ? b3 : 0.0f;
        out[OFF_FS + gi] = kv ? sc[sel] : 0.0f;
        out[OFF_VK + gi] = kv ? 1.0f : 0.0f;
    }
}

// ---------------------------------------------------------------------------
// Finalize: gather (maxv, idx) by sel, compute akpts. One thread per output.
// ---------------------------------------------------------------------------
__global__ __launch_bounds__(256) void finalize_kernel(
    const float* __restrict__ koff,   // [4,300,17,2]
    float* __restrict__ out)
{
    int i = blockIdx.x * 256 + threadIdx.x;   // (b, t, k) flattened
    if (i >= NROWS) return;
    int k  = i % NKPT;
    int gi = i / NKPT;
    int b  = gi / NRES;

    int sel = g_sel[gi];
    int kv  = g_kv[gi];
    int row = (b * NRES + sel) * NKPT + k;

    float mv = g_maxv[row];
    int   bi = g_midx[row];
    const float* ko = koff + (size_t)row * 2;

    float nx = fminf(fmaxf(__int2float_rn(bi % HMW) / (float)(HMW - 1) + ko[0], 0.0f), 1.0f);
    float ny = fminf(fmaxf(__int2float_rn(bi / HMW) / (float)(HMW - 1) + ko[1], 0.0f), 1.0f);

    float x1 = g_boxsel[gi * 4 + 0], y1 = g_boxsel[gi * 4 + 1];
    float x2 = g_boxsel[gi * 4 + 2], y2 = g_boxsel[gi * 4 + 3];
    float ax = x1 + nx * (x2 - x1);
    float ay = y1 + ny * (y2 - y1);

    float* o = out + OFF_AK + (size_t)i * 3;
    o[0] = kv ? ax : 0.0f;
    o[1] = kv ? ay : 0.0f;
    o[2] = kv ? mv : 0.0f;
}

// ---------------------------------------------------------------------------
extern "C" void kernel_launch(void* const* d_in, const int* in_sizes, int n_in,
                              void* d_out, int out_size)
{
    const float* logits = (const float*)d_in[0];  // pred_logits
    const float* boxes  = (const float*)d_in[1];  // pred_boxes
    const float* hm     = (const float*)d_in[2];  // pred_keypoint_heatmaps
    const float* koff   = (const float*)d_in[3];  // pred_keypoint_offsets
    const float* sizes  = (const float*)d_in[4];  // orig_target_sizes
    float* out = (float*)d_out;

    main_kernel<<<BB + NROWS, 256>>>(logits, boxes, sizes, hm, out);
    finalize_kernel<<<(NROWS + 255) / 256, 256>>>(koff, out);
}